// round 3
// baseline (speedup 1.0000x reference)
#include <cuda_runtime.h>

// TripletLoss with per-class margins.
//   d_ap = ||a - p + 1e-6||_2, d_an = ||a - n + 1e-6||_2  (eps per element)
//   loss = mean(max(d_ap - d_an + margins[c], 0))
// Inputs: anchors [B,128] f32, poss [B,128] f32, negs [B,128] f32, cs [B] int.
// cs nominal dtype is int64, but JAX without x64 demotes to int32 — we probe
// the memory layout at runtime (deterministic, graph-capturable).

#define EPS 1e-6f
#define D 128

__constant__ float c_margins[4] = {0.1f, 0.085f, 0.07f, 0.04f};

__device__ double g_sum;
__device__ int g_cs_is_i32;   // 1 if cs is packed int32, 0 if int64 (little-endian)

__global__ void zero_kernel() { g_sum = 0.0; }

// Probe: if cs is int64 (values 0..3), every odd int32 word is 0.
// If cs is int32, odd words are class values (nonzero with prob 3/4 each).
// Scan 2048 odd words: any nonzero -> int32 layout.
__global__ void detect_kernel(const int* __restrict__ cs32, int B)
{
    __shared__ int found;
    if (threadIdx.x == 0) found = 0;
    __syncthreads();
    const int limit = (B < 4096) ? B : 4096;   // safe in both layouts
    for (int i = 1 + 2 * threadIdx.x; i < limit; i += 2 * blockDim.x) {
        if (cs32[i] != 0) found = 1;
    }
    __syncthreads();
    if (threadIdx.x == 0) g_cs_is_i32 = found;
}

__device__ __forceinline__ void row_sums(const float4 av, const float4 pv,
                                         const float4 nv, float& sap, float& san)
{
    float d;
    d = av.x - pv.x + EPS; sap = d * d;
    d = av.y - pv.y + EPS; sap = fmaf(d, d, sap);
    d = av.z - pv.z + EPS; sap = fmaf(d, d, sap);
    d = av.w - pv.w + EPS; sap = fmaf(d, d, sap);

    d = av.x - nv.x + EPS; san = d * d;
    d = av.y - nv.y + EPS; san = fmaf(d, d, san);
    d = av.z - nv.z + EPS; san = fmaf(d, d, san);
    d = av.w - nv.w + EPS; san = fmaf(d, d, san);
}

__global__ void __launch_bounds__(256) triplet_kernel(
    const float* __restrict__ a,
    const float* __restrict__ p,
    const float* __restrict__ n,
    const int* __restrict__ cs32,
    int B)
{
    const int lane = threadIdx.x & 31;
    const int warp = threadIdx.x >> 5;
    const int warps_per_block = blockDim.x >> 5;
    const int gwarp = blockIdx.x * warps_per_block + warp;
    const int nwarps = gridDim.x * warps_per_block;

    // cs index stride: 1 for int32 layout, 2 for int64 (low word holds value).
    const int cstride = g_cs_is_i32 ? 1 : 2;

    float local = 0.0f;

    int row = gwarp * 2;
    const int stride = nwarps * 2;

    for (; row + 1 < B; row += stride) {
        const size_t b0 = (size_t)row * D + lane * 4;
        const size_t b1 = b0 + D;

        // 6 front-batched LDG.128 per lane: high MLP ahead of shfl chain.
        const float4 av0 = *reinterpret_cast<const float4*>(a + b0);
        const float4 pv0 = *reinterpret_cast<const float4*>(p + b0);
        const float4 nv0 = *reinterpret_cast<const float4*>(n + b0);
        const float4 av1 = *reinterpret_cast<const float4*>(a + b1);
        const float4 pv1 = *reinterpret_cast<const float4*>(p + b1);
        const float4 nv1 = *reinterpret_cast<const float4*>(n + b1);

        float sap0, san0, sap1, san1;
        row_sums(av0, pv0, nv0, sap0, san0);
        row_sums(av1, pv1, nv1, sap1, san1);

        #pragma unroll
        for (int off = 16; off > 0; off >>= 1) {
            sap0 += __shfl_xor_sync(0xffffffffu, sap0, off);
            san0 += __shfl_xor_sync(0xffffffffu, san0, off);
            sap1 += __shfl_xor_sync(0xffffffffu, sap1, off);
            san1 += __shfl_xor_sync(0xffffffffu, san1, off);
        }

        if (lane == 0) {
            const int c0 = cs32[(size_t)row * cstride] & 3;
            const int c1 = cs32[(size_t)(row + 1) * cstride] & 3;
            local += fmaxf(sqrtf(sap0) - sqrtf(san0) + c_margins[c0], 0.0f);
            local += fmaxf(sqrtf(sap1) - sqrtf(san1) + c_margins[c1], 0.0f);
        }
    }

    if (row < B) {
        const size_t b0 = (size_t)row * D + lane * 4;
        const float4 av = *reinterpret_cast<const float4*>(a + b0);
        const float4 pv = *reinterpret_cast<const float4*>(p + b0);
        const float4 nv = *reinterpret_cast<const float4*>(n + b0);
        float sap, san;
        row_sums(av, pv, nv, sap, san);
        #pragma unroll
        for (int off = 16; off > 0; off >>= 1) {
            sap += __shfl_xor_sync(0xffffffffu, sap, off);
            san += __shfl_xor_sync(0xffffffffu, san, off);
        }
        if (lane == 0) {
            const int c = cs32[(size_t)row * cstride] & 3;
            local += fmaxf(sqrtf(sap) - sqrtf(san) + c_margins[c], 0.0f);
        }
    }

    __shared__ float s_part[32];
    if (lane == 0) s_part[warp] = local;
    __syncthreads();

    if (warp == 0) {
        float v = (lane < warps_per_block) ? s_part[lane] : 0.0f;
        #pragma unroll
        for (int off = 16; off > 0; off >>= 1)
            v += __shfl_xor_sync(0xffffffffu, v, off);
        if (lane == 0)
            atomicAdd(&g_sum, (double)v);
    }
}

__global__ void finalize_kernel(float* out, float inv_b) {
    *out = (float)(g_sum * (double)inv_b);
}

extern "C" void kernel_launch(void* const* d_in, const int* in_sizes, int n_in,
                              void* d_out, int out_size)
{
    const float* anchors = (const float*)d_in[0];
    const float* poss    = (const float*)d_in[1];
    const float* negs    = (const float*)d_in[2];
    const int*   cs32    = (const int*)d_in[3];
    float* out = (float*)d_out;

    const int B = in_sizes[3];  // cs element count = B

    zero_kernel<<<1, 1>>>();
    detect_kernel<<<1, 256>>>(cs32, B);

    const int threads = 256;
    const int blocks = 2048;  // 8 warps/block * 2048 = 16384 warps
    triplet_kernel<<<blocks, threads>>>(anchors, poss, negs, cs32, B);

    finalize_kernel<<<1, 1>>>(out, 1.0f / (float)B);
}

// round 4
// speedup vs baseline: 1.0324x; 1.0324x over previous
#include <cuda_runtime.h>

// TripletLoss with per-class margins — single fused kernel.
//   d_ap = ||a - p + 1e-6||_2, d_an = ||a - n + 1e-6||_2  (eps per element)
//   out  = mean(max(d_ap - d_an + margins[c], 0))
// Inputs: anchors [B,128] f32, poss [B,128] f32, negs [B,128] f32, cs [B].
// cs nominal dtype is int64 but JAX default-demotes to int32; layout probed
// in-kernel (block-wide OR over odd int32 words).
//
// One launch total: per-block partials -> atomicAdd(g_sum) -> last block
// (completion counter) writes mean and resets state for the next graph replay.

#define EPS 1e-6f
#define D 128

__constant__ float c_margins[4] = {0.1f, 0.085f, 0.07f, 0.04f};

__device__ double g_sum = 0.0;          // statically zeroed; reset each launch
__device__ unsigned int g_count = 0u;

__device__ __forceinline__ void row_sums(const float4 av, const float4 pv,
                                         const float4 nv, float& sap, float& san)
{
    float d;
    d = av.x - pv.x + EPS; sap = d * d;
    d = av.y - pv.y + EPS; sap = fmaf(d, d, sap);
    d = av.z - pv.z + EPS; sap = fmaf(d, d, sap);
    d = av.w - pv.w + EPS; sap = fmaf(d, d, sap);

    d = av.x - nv.x + EPS; san = d * d;
    d = av.y - nv.y + EPS; san = fmaf(d, d, san);
    d = av.z - nv.z + EPS; san = fmaf(d, d, san);
    d = av.w - nv.w + EPS; san = fmaf(d, d, san);
}

__global__ void __launch_bounds__(256) triplet_fused_kernel(
    const float* __restrict__ a,
    const float* __restrict__ p,
    const float* __restrict__ n,
    const int* __restrict__ cs32,
    float* __restrict__ out,
    int B, float inv_b)
{
    const int lane = threadIdx.x & 31;
    const int warp = threadIdx.x >> 5;
    const int warps_per_block = blockDim.x >> 5;
    const int gwarp = blockIdx.x * warps_per_block + warp;
    const int nwarps = gridDim.x * warps_per_block;

    // ---- In-kernel cs layout probe ----
    // int64 little-endian with values 0..3 => every odd int32 word == 0.
    // int32 => odd words are class ids (nonzero w.p. 3/4 each).
    // 256 odd-word samples: misdetect prob (1/4)^256 ~ 0. L2-hot after block 0.
    int probe = 0;
    {
        const int limit = (B < 4096) ? B : 4096;  // in-bounds under both layouts
        const int i = 1 + 2 * (int)threadIdx.x;
        if (i < limit) probe = (cs32[i] != 0);
    }
    const int cstride = __syncthreads_or(probe) ? 1 : 2;

    // ---- Main streaming loop: one warp per row, 2 rows per iteration ----
    float local = 0.0f;
    int row = gwarp * 2;
    const int stride = nwarps * 2;

    for (; row + 1 < B; row += stride) {
        const size_t b0 = (size_t)row * D + lane * 4;
        const size_t b1 = b0 + D;

        // 6 front-batched streaming LDG.128 per lane (no reuse -> .cs).
        const float4 av0 = __ldcs(reinterpret_cast<const float4*>(a + b0));
        const float4 pv0 = __ldcs(reinterpret_cast<const float4*>(p + b0));
        const float4 nv0 = __ldcs(reinterpret_cast<const float4*>(n + b0));
        const float4 av1 = __ldcs(reinterpret_cast<const float4*>(a + b1));
        const float4 pv1 = __ldcs(reinterpret_cast<const float4*>(p + b1));
        const float4 nv1 = __ldcs(reinterpret_cast<const float4*>(n + b1));

        float sap0, san0, sap1, san1;
        row_sums(av0, pv0, nv0, sap0, san0);
        row_sums(av1, pv1, nv1, sap1, san1);

        #pragma unroll
        for (int off = 16; off > 0; off >>= 1) {
            sap0 += __shfl_xor_sync(0xffffffffu, sap0, off);
            san0 += __shfl_xor_sync(0xffffffffu, san0, off);
            sap1 += __shfl_xor_sync(0xffffffffu, sap1, off);
            san1 += __shfl_xor_sync(0xffffffffu, san1, off);
        }

        if (lane == 0) {
            const int c0 = cs32[(size_t)row * cstride] & 3;
            const int c1 = cs32[(size_t)(row + 1) * cstride] & 3;
            local += fmaxf(sqrtf(sap0) - sqrtf(san0) + c_margins[c0], 0.0f);
            local += fmaxf(sqrtf(sap1) - sqrtf(san1) + c_margins[c1], 0.0f);
        }
    }

    if (row < B) {  // tail row
        const size_t b0 = (size_t)row * D + lane * 4;
        const float4 av = __ldcs(reinterpret_cast<const float4*>(a + b0));
        const float4 pv = __ldcs(reinterpret_cast<const float4*>(p + b0));
        const float4 nv = __ldcs(reinterpret_cast<const float4*>(n + b0));
        float sap, san;
        row_sums(av, pv, nv, sap, san);
        #pragma unroll
        for (int off = 16; off > 0; off >>= 1) {
            sap += __shfl_xor_sync(0xffffffffu, sap, off);
            san += __shfl_xor_sync(0xffffffffu, san, off);
        }
        if (lane == 0) {
            const int c = cs32[(size_t)row * cstride] & 3;
            local += fmaxf(sqrtf(sap) - sqrtf(san) + c_margins[c], 0.0f);
        }
    }

    // ---- Block reduce ----
    __shared__ float s_part[32];
    if (lane == 0) s_part[warp] = local;
    __syncthreads();

    if (warp == 0) {
        float v = (lane < warps_per_block) ? s_part[lane] : 0.0f;
        #pragma unroll
        for (int off = 16; off > 0; off >>= 1)
            v += __shfl_xor_sync(0xffffffffu, v, off);

        // ---- Fused epilogue: last block writes the mean and resets state ----
        if (lane == 0) {
            atomicAdd(&g_sum, (double)v);
            __threadfence();
            const unsigned int old = atomicAdd(&g_count, 1u);
            if (old == gridDim.x - 1u) {
                const double s = atomicAdd(&g_sum, 0.0);  // ordered read
                *out = (float)(s * (double)inv_b);
                g_sum = 0.0;        // reset for next graph replay
                g_count = 0u;
                __threadfence();
            }
        }
    }
}

extern "C" void kernel_launch(void* const* d_in, const int* in_sizes, int n_in,
                              void* d_out, int out_size)
{
    const float* anchors = (const float*)d_in[0];
    const float* poss    = (const float*)d_in[1];
    const float* negs    = (const float*)d_in[2];
    const int*   cs32    = (const int*)d_in[3];
    float* out = (float*)d_out;

    const int B = in_sizes[3];  // cs element count = B

    const int threads = 256;
    const int blocks = 148 * 8;  // exactly one wave on 148 SMs (8 CTAs/SM)
    triplet_fused_kernel<<<blocks, threads>>>(anchors, poss, negs, cs32, out,
                                              B, 1.0f / (float)B);
}